// round 2
// baseline (speedup 1.0000x reference)
#include <cuda_runtime.h>
#include <cuda_bf16.h>
#include <cstdint>
#include <math.h>

#define L_SEQ 4096
#define H_DIM 1024
#define E_DIM 1024
#define H3    3072
#define T_DIM 512

#define RNN_NCTA 128
#define NIDX 16
#define NROW 48
#define RNN_THREADS 256

// ---------------- device scratch (no allocations allowed) ----------------
__device__ float g_gx[4][L_SEQ][H3];       // [sent*2+dir][t][3H]
__device__ float g_h[2][2][2][H_DIM];      // [buf][dir][sent][H]
__device__ float g_hs[4];
__device__ unsigned int g_bar;

// ---------------- helpers ----------------
__device__ __forceinline__ unsigned tf32_of(float f) {
  unsigned r; asm("cvt.rna.tf32.f32 %0, %1;" : "=r"(r) : "f"(f)); return r;
}
__device__ __forceinline__ void mma_tf32(float* c, const unsigned* a, const unsigned* b) {
  asm volatile("mma.sync.aligned.m16n8k8.row.col.f32.tf32.tf32.f32 "
    "{%0,%1,%2,%3},{%4,%5,%6,%7},{%8,%9},{%0,%1,%2,%3};"
    : "+f"(c[0]), "+f"(c[1]), "+f"(c[2]), "+f"(c[3])
    : "r"(a[0]), "r"(a[1]), "r"(a[2]), "r"(a[3]), "r"(b[0]), "r"(b[1]));
}
__device__ __forceinline__ float sigm(float x) { return 1.f / (1.f + __expf(-x)); }

// ---------------- init ----------------
__global__ void init_kernel(const float* __restrict__ hidden) {
  int i = blockIdx.x * blockDim.x + threadIdx.x;
  if (i == 0) g_bar = 0u;
  if (i < 4) g_hs[i] = 0.f;
  if (i < 2 * H_DIM) {
    int d = i / H_DIM, j = i % H_DIM;
    g_h[0][d][0][j] = hidden[i];
    g_h[0][d][1][j] = hidden[i];
  }
}

// ---------------- gx GEMM ----------------
// gx[z][t][:] = emb[toks[t]] @ W^T + b_ih  (+ b_hh folded in for r,z gate cols)
__global__ __launch_bounds__(256) void gemm_gx(
    const int* __restrict__ sA, const int* __restrict__ sB,
    const float* __restrict__ emb,
    const float* __restrict__ wf, const float* __restrict__ wr,
    const float* __restrict__ bihf, const float* __restrict__ bhhf,
    const float* __restrict__ bihr, const float* __restrict__ bhhr) {
  __shared__ float As[128][17];
  __shared__ float Bs[128][17];

  int z = blockIdx.z;
  const int*   toks = (z >> 1) ? sB : sA;
  const float* W    = (z & 1) ? wr   : wf;
  const float* bih  = (z & 1) ? bihr : bihf;
  const float* bhh  = (z & 1) ? bhhr : bhhf;

  int m0 = blockIdx.y * 128, n0 = blockIdx.x * 128;
  int tid = threadIdx.x, lane = tid & 31, warp = tid >> 5;
  int wm = warp & 3, wn = warp >> 2;        // 4x2 warps -> 32x64 warp tiles
  int gid = lane >> 2, tig = lane & 3;

  int ar = tid >> 1, ac = (tid & 1) * 8;
  const float* aSrc = emb + (size_t)toks[m0 + ar] * E_DIM + ac;
  const float* bSrc = W   + (size_t)(n0 + ar) * E_DIM + ac;

  float c[2][8][4];
  #pragma unroll
  for (int mi = 0; mi < 2; mi++)
    #pragma unroll
    for (int ni = 0; ni < 8; ni++)
      #pragma unroll
      for (int q = 0; q < 4; q++) c[mi][ni][q] = 0.f;

  for (int k0 = 0; k0 < E_DIM; k0 += 16) {
    float4 av0 = *(const float4*)(aSrc + k0);
    float4 av1 = *(const float4*)(aSrc + k0 + 4);
    float4 bv0 = *(const float4*)(bSrc + k0);
    float4 bv1 = *(const float4*)(bSrc + k0 + 4);
    __syncthreads();
    As[ar][ac+0]=av0.x; As[ar][ac+1]=av0.y; As[ar][ac+2]=av0.z; As[ar][ac+3]=av0.w;
    As[ar][ac+4]=av1.x; As[ar][ac+5]=av1.y; As[ar][ac+6]=av1.z; As[ar][ac+7]=av1.w;
    Bs[ar][ac+0]=bv0.x; Bs[ar][ac+1]=bv0.y; Bs[ar][ac+2]=bv0.z; Bs[ar][ac+3]=bv0.w;
    Bs[ar][ac+4]=bv1.x; Bs[ar][ac+5]=bv1.y; Bs[ar][ac+6]=bv1.z; Bs[ar][ac+7]=bv1.w;
    __syncthreads();

    #pragma unroll
    for (int kk = 0; kk < 16; kk += 8) {
      unsigned a[2][4];
      #pragma unroll
      for (int mi = 0; mi < 2; mi++) {
        int r0 = wm * 32 + mi * 16 + gid;
        a[mi][0] = tf32_of(As[r0    ][kk + tig    ]);
        a[mi][1] = tf32_of(As[r0 + 8][kk + tig    ]);
        a[mi][2] = tf32_of(As[r0    ][kk + tig + 4]);
        a[mi][3] = tf32_of(As[r0 + 8][kk + tig + 4]);
      }
      unsigned b[8][2];
      #pragma unroll
      for (int ni = 0; ni < 8; ni++) {
        int cc = wn * 64 + ni * 8 + gid;
        b[ni][0] = tf32_of(Bs[cc][kk + tig    ]);
        b[ni][1] = tf32_of(Bs[cc][kk + tig + 4]);
      }
      #pragma unroll
      for (int mi = 0; mi < 2; mi++)
        #pragma unroll
        for (int ni = 0; ni < 8; ni++)
          mma_tf32(c[mi][ni], a[mi], b[ni]);
    }
  }

  #pragma unroll
  for (int mi = 0; mi < 2; mi++) {
    int row = m0 + wm * 32 + mi * 16 + gid;
    #pragma unroll
    for (int ni = 0; ni < 8; ni++) {
      int colb = n0 + wn * 64 + ni * 8 + 2 * tig;
      float bb0 = bih[colb]     + (colb     < 2 * H_DIM ? bhh[colb]     : 0.f);
      float bb1 = bih[colb + 1] + (colb + 1 < 2 * H_DIM ? bhh[colb + 1] : 0.f);
      float2 v0 = make_float2(c[mi][ni][0] + bb0, c[mi][ni][1] + bb1);
      float2 v1 = make_float2(c[mi][ni][2] + bb0, c[mi][ni][3] + bb1);
      *(float2*)&g_gx[z][row    ][colb] = v0;
      *(float2*)&g_gx[z][row + 8][colb] = v1;
    }
  }
}

// ---------------- persistent GRU recurrence ----------------
extern __shared__ float s_dyn[];

__global__ __launch_bounds__(RNN_THREADS, 1) void rnn_kernel(
    const float* __restrict__ whf, const float* __restrict__ whr,
    const float* __restrict__ bhhf, const float* __restrict__ bhhr) {
  float* sW  = s_dyn;                    // NROW * H_DIM
  float* sGh = sW + NROW * H_DIM;        // 2 * NROW
  float* sH  = sGh + 2 * NROW;           // 2 * H_DIM

  int cta  = blockIdx.x;
  int d    = cta >> 6;                   // 0 = fwd, 1 = rev
  int i0   = (cta & 63) * NIDX;
  const float* Wh = d ? whr : whf;
  int tid = threadIdx.x, lane = tid & 31, warp = tid >> 5;

  // stage w_hh rows into SMEM (once)
  for (int r = 0; r < NROW; r++) {
    int g = r >> 4, li = r & 15;
    const float* src = Wh + (size_t)(g * H_DIM + i0 + li) * H_DIM;
    for (int k = tid; k < H_DIM; k += RNN_THREADS) sW[r * H_DIM + k] = src[k];
  }

  bool isGate = tid < 2 * NIDX;          // 32 gate threads
  int gs = tid & 1, gli = tid >> 1;
  float bhn = 0.f;
  if (isGate) bhn = (d ? bhhr : bhhf)[2 * H_DIM + i0 + gli];

  {
    const float* hsrc = &g_h[0][d][0][0];
    for (int k = tid; k < 2 * H_DIM; k += RNN_THREADS) sH[k] = hsrc[k];
  }
  __syncthreads();
  float hA[32], hB[32];
  #pragma unroll
  for (int j = 0; j < 32; j++) { hA[j] = sH[j * 32 + lane]; hB[j] = sH[H_DIM + j * 32 + lane]; }

  for (int t = 0; t < L_SEQ; t++) {
    int nxt = (t + 1) & 1;

    // prefetch gx + hold (independent of this step's dots)
    float gxr = 0.f, gxz = 0.f, gxn = 0.f, hold = 0.f;
    if (isGate) {
      int trow = d ? (L_SEQ - 1 - t) : t;
      const float* gxp = &g_gx[gs * 2 + d][trow][0];
      gxr  = gxp[i0 + gli];
      gxz  = gxp[H_DIM + i0 + gli];
      gxn  = gxp[2 * H_DIM + i0 + gli];
      hold = sH[gs * H_DIM + i0 + gli];
    }

    // 48 rows x 2 sentences
    #pragma unroll
    for (int rr = 0; rr < 6; rr++) {
      int r = warp + rr * 8;
      const float* wl = sW + r * H_DIM + lane;
      float a0 = 0.f, a1 = 0.f, b0 = 0.f, b1 = 0.f;
      #pragma unroll
      for (int j = 0; j < 32; j += 2) {
        float w0 = wl[j * 32], w1 = wl[(j + 1) * 32];
        a0 += w0 * hA[j];     b0 += w0 * hB[j];
        a1 += w1 * hA[j + 1]; b1 += w1 * hB[j + 1];
      }
      float va = a0 + a1, vb = b0 + b1;
      #pragma unroll
      for (int off = 16; off > 0; off >>= 1) {
        va += __shfl_xor_sync(0xffffffffu, va, off);
        vb += __shfl_xor_sync(0xffffffffu, vb, off);
      }
      if (lane == 0) { sGh[r] = va; sGh[NROW + r] = vb; }
    }
    __syncthreads();   // sGh ready

    if (isGate) {
      float ghr = sGh[gs * NROW + gli];
      float ghz = sGh[gs * NROW + NIDX + gli];
      float ghn = sGh[gs * NROW + 2 * NIDX + gli];
      float r_ = sigm(gxr + ghr);
      float z_ = sigm(gxz + ghz);
      float ag = gxn + r_ * (ghn + bhn);
      ag = fminf(fmaxf(ag, -15.f), 15.f);
      float e = __expf(-2.f * ag);
      float n_ = (1.f - e) / (1.f + e);
      g_h[nxt][d][gs][i0 + gli] = (1.f - z_) * n_ + z_ * hold;
    }
    __syncthreads();   // all g_h writes done (cta scope)

    if (tid == 0) {
      __threadfence();
      atomicAdd(&g_bar, 1u);
      unsigned int target = (unsigned)(t + 1) * RNN_NCTA;
      unsigned int v;
      do {
        asm volatile("ld.acquire.gpu.u32 %0, [%1];" : "=r"(v) : "l"(&g_bar) : "memory");
      } while (v < target);
    }
    __syncthreads();   // barrier done for whole CTA

    {
      const float* hsrc = &g_h[nxt][d][0][0];
      for (int k = tid; k < 2 * H_DIM; k += RNN_THREADS) sH[k] = hsrc[k];
    }
    __syncthreads();
    #pragma unroll
    for (int j = 0; j < 32; j++) { hA[j] = sH[j * 32 + lane]; hB[j] = sH[H_DIM + j * 32 + lane]; }
  }
}

// ---------------- head ----------------
__global__ __launch_bounds__(256) void head1(const float* __restrict__ W2,
                                             const float* __restrict__ b2) {
  __shared__ float ht[H_DIM];
  __shared__ float wsum[8];
  int j = blockIdx.x, tid = threadIdx.x, lane = tid & 31, warp = tid >> 5;
  // final h lives in buffer 0 (L_SEQ even)
  const float* fA = (j < 2) ? &g_h[0][0][0][0] : &g_h[0][1][0][0];
  const float* fB = (j < 2) ? &g_h[0][0][1][0] : &g_h[0][1][1][0];
  for (int k = tid; k < H_DIM; k += 256) {
    float a = fA[k], b = fB[k];
    ht[k] = (j & 1) ? a * b : fabsf(a - b);
  }
  __syncthreads();
  float acc = 0.f;
  for (int t = tid; t < T_DIM; t += 256) {
    float dsum = b2[t];
    const float* w = W2 + (size_t)t * H_DIM;
    #pragma unroll 4
    for (int k = 0; k < H_DIM; k++) dsum += ht[k] * w[k];
    acc += fmaxf(dsum, 0.f);
  }
  #pragma unroll
  for (int off = 16; off > 0; off >>= 1) acc += __shfl_xor_sync(0xffffffffu, acc, off);
  if (lane == 0) wsum[warp] = acc;
  __syncthreads();
  if (tid == 0) {
    float s = 0.f;
    #pragma unroll
    for (int w = 0; w < 8; w++) s += wsum[w];
    g_hs[j] = s;
  }
}

__global__ void head2(const float* __restrict__ Wl, const float* __restrict__ bl,
                      float* __restrict__ out) {
  float s = bl[0];
  #pragma unroll
  for (int j = 0; j < 4; j++) s += g_hs[j] * Wl[j];
  out[0] = 1.f / (1.f + __expf(-s));
}

// ---------------- launch ----------------
extern "C" void kernel_launch(void* const* d_in, const int* in_sizes, int n_in,
                              void* d_out, int out_size) {
  const int*   sentA  = (const int*)d_in[0];
  const int*   sentB  = (const int*)d_in[1];
  const float* hidden = (const float*)d_in[2];
  const float* emb    = (const float*)d_in[3];
  const float* w_ih_f = (const float*)d_in[4];
  const float* w_hh_f = (const float*)d_in[5];
  const float* b_ih_f = (const float*)d_in[6];
  const float* b_hh_f = (const float*)d_in[7];
  const float* w_ih_r = (const float*)d_in[8];
  const float* w_hh_r = (const float*)d_in[9];
  const float* b_ih_r = (const float*)d_in[10];
  const float* b_hh_r = (const float*)d_in[11];
  const float* W2     = (const float*)d_in[12];
  const float* b2     = (const float*)d_in[13];
  const float* Wl     = (const float*)d_in[14];
  const float* bl     = (const float*)d_in[15];
  float* out = (float*)d_out;

  int rnn_smem = (NROW * H_DIM + 2 * NROW + 2 * H_DIM) * (int)sizeof(float);
  cudaFuncSetAttribute(rnn_kernel, cudaFuncAttributeMaxDynamicSharedMemorySize, rnn_smem);

  init_kernel<<<8, 256>>>(hidden);

  dim3 ggrid(H3 / 128, L_SEQ / 128, 4);
  gemm_gx<<<ggrid, 256>>>(sentA, sentB, emb, w_ih_f, w_ih_r,
                          b_ih_f, b_hh_f, b_ih_r, b_hh_r);

  rnn_kernel<<<RNN_NCTA, RNN_THREADS, rnn_smem>>>(w_hh_f, w_hh_r, b_hh_f, b_hh_r);

  head1<<<4, 256>>>(W2, b2);
  head2<<<1, 1>>>(Wl, bl, out);
}